// round 4
// baseline (speedup 1.0000x reference)
#include <cuda_runtime.h>
#include <math.h>

// Problem constants
#define BATCH   2
#define HW      64
#define NPIX    4096
#define BN      8192
#define DIMQ    64
#define CLD     128
#define KTOK    8
#define FLOW_SZ 1048576       // 2*2*512*512

// ---- device scratch ----
__device__ __align__(16) float g_w1t[81 * 64];   // g_w1t[c*64+o] = fte_w1[o*81+c]
__device__ __align__(16) float g_w2t[64 * 64];   // g_w2t[c*64+o] = fte_w2[o*64+c]
__device__ __align__(16) float k_scratch[BN * KTOK * DIMQ];   // 16MB
__device__ __align__(16) float v_scratch[BN * KTOK * DIMQ];   // 16MB
__device__ __align__(16) unsigned wk_hi_g[CLD * DIMQ];
__device__ __align__(16) unsigned wk_lo_g[CLD * DIMQ];
__device__ __align__(16) unsigned wv_hi_g[CLD * DIMQ];
__device__ __align__(16) unsigned wv_lo_g[CLD * DIMQ];

__device__ __forceinline__ float gelu_exact(float x) {
    return 0.5f * x * (1.0f + erff(x * 0.70710678118654752f));
}

__device__ __forceinline__ unsigned f2tf(float x) {
    unsigned r;
    asm("cvt.rna.tf32.f32 %0, %1;" : "=r"(r) : "f"(x));
    return r;
}

__device__ __forceinline__ void mma_tf32(float* d, const unsigned* a, unsigned b0, unsigned b1) {
    asm volatile(
        "mma.sync.aligned.m16n8k8.row.col.f32.tf32.tf32.f32 "
        "{%0,%1,%2,%3}, {%4,%5,%6,%7}, {%8,%9}, {%0,%1,%2,%3};"
        : "+f"(d[0]), "+f"(d[1]), "+f"(d[2]), "+f"(d[3])
        : "r"(a[0]), "r"(a[1]), "r"(a[2]), "r"(a[3]), "r"(b0), "r"(b1));
}

__device__ __forceinline__ float samp_map(const float* __restrict__ p, int ix, int iy) {
    if ((unsigned)ix < 64u && (unsigned)iy < 64u) return p[iy * 64 + ix];
    return 0.0f;
}

// ============================================================================
// K/V projection GEMM: [65536 x 128] @ [128 x 64] -> k_scratch / v_scratch
// 3-term TF32 split (hi*hi + hi*lo + lo*hi) for fp32-equivalent precision.
// Block: 256 threads = 8 warps arranged 2(m) x 4(n); warp tile 64 x 16.
// ============================================================================
__global__ __launch_bounds__(256) void kv_gemm(
    const float* __restrict__ A,      // cost_memory [65536][128]
    const float* __restrict__ bk,
    const float* __restrict__ bv)
{
    const int warp = threadIdx.x >> 5;
    const int lane = threadIdx.x & 31;
    const int wm = warp >> 2;          // 0..1
    const int wn = warp & 3;           // 0..3
    const int row0 = blockIdx.x * 128 + wm * 64;
    const int tg  = lane & 3;          // threadID_in_group
    const int gid = lane >> 2;         // groupID

    float kacc[4][2][4];
    float vacc[4][2][4];
    #pragma unroll
    for (int mt = 0; mt < 4; ++mt)
        #pragma unroll
        for (int nt = 0; nt < 2; ++nt)
            #pragma unroll
            for (int r = 0; r < 4; ++r) { kacc[mt][nt][r] = 0.f; vacc[mt][nt][r] = 0.f; }

    const float* Abase = A + (size_t)(row0 + gid) * 128 + tg;

    #pragma unroll 1
    for (int ks = 0; ks < 16; ++ks) {
        const int k0 = ks * 8;

        unsigned ahi[4][4], alo[4][4];
        #pragma unroll
        for (int mt = 0; mt < 4; ++mt) {
            const float* p = Abase + (size_t)mt * 16 * 128 + k0;
            float x0 = p[0];
            float x1 = p[8 * 128];
            float x2 = p[4];
            float x3 = p[8 * 128 + 4];
            ahi[mt][0] = f2tf(x0); alo[mt][0] = f2tf(x0 - __uint_as_float(ahi[mt][0]));
            ahi[mt][1] = f2tf(x1); alo[mt][1] = f2tf(x1 - __uint_as_float(ahi[mt][1]));
            ahi[mt][2] = f2tf(x2); alo[mt][2] = f2tf(x2 - __uint_as_float(ahi[mt][2]));
            ahi[mt][3] = f2tf(x3); alo[mt][3] = f2tf(x3 - __uint_as_float(ahi[mt][3]));
        }

        #pragma unroll
        for (int nt = 0; nt < 2; ++nt) {
            const int nn = wn * 16 + nt * 8 + gid;
            const int kk = k0 + tg;
            const int i0 = kk * 64 + nn;
            const int i1 = (kk + 4) * 64 + nn;
            unsigned bkh0 = wk_hi_g[i0], bkh1 = wk_hi_g[i1];
            unsigned bkl0 = wk_lo_g[i0], bkl1 = wk_lo_g[i1];
            unsigned bvh0 = wv_hi_g[i0], bvh1 = wv_hi_g[i1];
            unsigned bvl0 = wv_lo_g[i0], bvl1 = wv_lo_g[i1];
            #pragma unroll
            for (int mt = 0; mt < 4; ++mt) {
                mma_tf32(kacc[mt][nt], ahi[mt], bkh0, bkh1);
                mma_tf32(kacc[mt][nt], ahi[mt], bkl0, bkl1);
                mma_tf32(kacc[mt][nt], alo[mt], bkh0, bkh1);
                mma_tf32(vacc[mt][nt], ahi[mt], bvh0, bvh1);
                mma_tf32(vacc[mt][nt], ahi[mt], bvl0, bvl1);
                mma_tf32(vacc[mt][nt], alo[mt], bvh0, bvh1);
            }
        }
    }

    // epilogue: add bias, store float2 pairs
    #pragma unroll
    for (int nt = 0; nt < 2; ++nt) {
        const int cc = wn * 16 + nt * 8 + 2 * tg;
        const float2 bk2 = *(const float2*)(bk + cc);
        const float2 bv2 = *(const float2*)(bv + cc);
        #pragma unroll
        for (int mt = 0; mt < 4; ++mt) {
            const int r = row0 + mt * 16 + gid;
            float2 k01 = make_float2(kacc[mt][nt][0] + bk2.x, kacc[mt][nt][1] + bk2.y);
            float2 k23 = make_float2(kacc[mt][nt][2] + bk2.x, kacc[mt][nt][3] + bk2.y);
            float2 v01 = make_float2(vacc[mt][nt][0] + bv2.x, vacc[mt][nt][1] + bv2.y);
            float2 v23 = make_float2(vacc[mt][nt][2] + bv2.x, vacc[mt][nt][3] + bv2.y);
            *(float2*)(k_scratch + (size_t)r * 64 + cc)       = k01;
            *(float2*)(k_scratch + (size_t)(r + 8) * 64 + cc) = k23;
            *(float2*)(v_scratch + (size_t)r * 64 + cc)       = v01;
            *(float2*)(v_scratch + (size_t)(r + 8) * 64 + cc) = v23;
        }
    }
}

// ============================================================================
// Decoder (per-token): K/V already computed; everything else fp32 scalar.
// ============================================================================
struct TokSmem {
    float kv[1024];     // k_s[0..511], v_s[512..1023]
    float corr[96];     // corr[81]; later reused as attn[64]
    float bufA[64];
    float bufB[64];
    float qlin[64];
    float short_s[64];
    float x_s[64];
};

__global__ __launch_bounds__(128) void decoder_kernel(
    const float* __restrict__ cost_maps,
    const float* __restrict__ coords1,
    const float* __restrict__ fte_b1,
    const float* __restrict__ fte_b2,
    const float* __restrict__ ln1_g, const float* __restrict__ ln1_b,
    const float* __restrict__ ln2_g, const float* __restrict__ ln2_b,
    const float* __restrict__ wq,  const float* __restrict__ bq,
    const float* __restrict__ wp,  const float* __restrict__ bp,
    const float* __restrict__ fw1, const float* __restrict__ fb1,
    const float* __restrict__ fw2, const float* __restrict__ fb2,
    float* __restrict__ out)
{
    __shared__ TokSmem ts[4];
    const int warp = threadIdx.x >> 5;
    const int lane = threadIdx.x & 31;
    const int n    = blockIdx.x * 4 + warp;
    TokSmem& S = ts[warp];

    const int b   = n >> 12;
    const int pix = n & 4095;
    const float cx = coords1[b * 8192 + pix];
    const float cy = coords1[b * 8192 + 4096 + pix];
    const int o0 = lane, o1 = lane + 32;

    // ---- load precomputed K/V (coalesced float4) ----
    {
        const float4* ks4 = (const float4*)(k_scratch + (size_t)n * 512);
        const float4* vs4 = (const float4*)(v_scratch + (size_t)n * 512);
        float4* d4 = (float4*)S.kv;
        #pragma unroll
        for (int t = 0; t < 4; ++t) d4[lane + t * 32] = ks4[lane + t * 32];
        #pragma unroll
        for (int t = 0; t < 4; ++t) d4[128 + lane + t * 32] = vs4[lane + t * 32];
    }

    // ---- bilinear correlation sampling: 81 samples ----
    {
        const float* cmap = cost_maps + (size_t)n * 4096;
        for (int s = lane; s < 81; s += 32) {
            int si = s / 9, sj = s - si * 9;
            float px = cx + (float)(si - 4);
            float py = cy + (float)(sj - 4);
            float fx0 = floorf(px), fy0 = floorf(py);
            float wx = px - fx0, wy = py - fy0;
            int ix = (int)fx0, iy = (int)fy0;
            float v00 = samp_map(cmap, ix,     iy);
            float v10 = samp_map(cmap, ix + 1, iy);
            float v01 = samp_map(cmap, ix,     iy + 1);
            float v11 = samp_map(cmap, ix + 1, iy + 1);
            S.corr[s] = v00 * (1.f - wx) * (1.f - wy) + v10 * wx * (1.f - wy)
                      + v01 * (1.f - wx) * wy         + v11 * wx * wy;
        }
    }
    __syncwarp();

    // ---- flow token encoder: q1 = gelu(W1 @ corr + b1) ----
    {
        float a0 = fte_b1[o0], a1 = fte_b1[o1];
        #pragma unroll 3
        for (int c = 0; c < 81; ++c) {
            float cr = S.corr[c];
            a0 = fmaf(cr, g_w1t[c * 64 + o0], a0);
            a1 = fmaf(cr, g_w1t[c * 64 + o1], a1);
        }
        S.bufA[o0] = gelu_exact(a0);
        S.bufA[o1] = gelu_exact(a1);
    }
    __syncwarp();

    // ---- q2 = W2 @ q1 + b2  (= query = short) ----
    float q0 = fte_b2[o0], q1v = fte_b2[o1];
    #pragma unroll 4
    for (int c = 0; c < 64; ++c) {
        float t = S.bufA[c];
        q0  = fmaf(t, g_w2t[c * 64 + o0], q0);
        q1v = fmaf(t, g_w2t[c * 64 + o1], q1v);
    }
    S.short_s[o0] = q0;
    S.short_s[o1] = q1v;

    // ---- layernorm1 + positional encoding ----
    {
        float sm = q0 + q1v;
        #pragma unroll
        for (int off = 16; off; off >>= 1) sm += __shfl_xor_sync(0xffffffffu, sm, off);
        float mean = sm * (1.0f / 64.0f);
        float d0 = q0 - mean, d1 = q1v - mean;
        float vs = d0 * d0 + d1 * d1;
        #pragma unroll
        for (int off = 16; off; off >>= 1) vs += __shfl_xor_sync(0xffffffffu, vs, off);
        float inv = rsqrtf(vs * (1.0f / 64.0f) + 1e-5f);

        float enc0, enc1;
        {
            int r = o0 >> 4, f = o0 & 15;
            float base = (r < 2) ? cx : cy;
            float ang = 3.14f * base * (float)f / 200.0f;
            enc0 = ((r & 1) == 0) ? sinf(ang) : cosf(ang);
        }
        {
            int r = o1 >> 4, f = o1 & 15;
            float base = (r < 2) ? cx : cy;
            float ang = 3.14f * base * (float)f / 200.0f;
            enc1 = ((r & 1) == 0) ? sinf(ang) : cosf(ang);
        }
        S.bufB[o0] = d0 * inv * ln1_g[o0] + ln1_b[o0] + enc0;
        S.bufB[o1] = d1 * inv * ln1_g[o1] + ln1_b[o1] + enc1;
    }
    __syncwarp();

    // ---- q projection ----
    {
        float a0 = bq[o0], a1 = bq[o1];
        #pragma unroll 4
        for (int i = 0; i < 64; ++i) {
            float xv = S.bufB[i];
            a0 = fmaf(xv, wq[i * 64 + o0], a0);
            a1 = fmaf(xv, wq[i * 64 + o1], a1);
        }
        S.qlin[o0] = a0;
        S.qlin[o1] = a1;
    }
    __syncwarp();

    // ---- attention: heads=8, hd=8, K=8 ----
    {
        const float* k_s = S.kv;
        int h0 = lane >> 3, jj = lane & 7;
        int h1 = h0 + 4;
        float s0 = 0.f, s1 = 0.f;
        #pragma unroll
        for (int d = 0; d < 8; ++d) {
            s0 = fmaf(S.qlin[h0 * 8 + d], k_s[jj * 64 + h0 * 8 + d], s0);
            s1 = fmaf(S.qlin[h1 * 8 + d], k_s[jj * 64 + h1 * 8 + d], s1);
        }
        s0 *= 0.35355339059327373f;
        s1 *= 0.35355339059327373f;
        float m0 = s0, m1 = s1;
        #pragma unroll
        for (int off = 4; off; off >>= 1) {
            m0 = fmaxf(m0, __shfl_xor_sync(0xffffffffu, m0, off));
            m1 = fmaxf(m1, __shfl_xor_sync(0xffffffffu, m1, off));
        }
        float e0 = expf(s0 - m0), e1 = expf(s1 - m1);
        float t0 = e0, t1 = e1;
        #pragma unroll
        for (int off = 4; off; off >>= 1) {
            t0 += __shfl_xor_sync(0xffffffffu, t0, off);
            t1 += __shfl_xor_sync(0xffffffffu, t1, off);
        }
        S.corr[h0 * 8 + jj] = e0 / t0;    // attn reuses corr buffer
        S.corr[h1 * 8 + jj] = e1 / t1;
    }
    __syncwarp();

    // ---- attn @ V ----
    {
        const float* v_s = S.kv + 512;
        float a0 = 0.f, a1 = 0.f;
        int h0 = o0 >> 3, h1 = o1 >> 3;
        #pragma unroll
        for (int j = 0; j < 8; ++j) {
            a0 = fmaf(S.corr[h0 * 8 + j], v_s[j * 64 + o0], a0);
            a1 = fmaf(S.corr[h1 * 8 + j], v_s[j * 64 + o1], a1);
        }
        S.bufA[o0] = a0;
        S.bufA[o1] = a1;
    }
    __syncwarp();

    // ---- proj: x = concat(out, short) @ wp + bp + short ----
    float x0 = bp[o0], x1 = bp[o1];
    #pragma unroll 4
    for (int i = 0; i < 64; ++i) {
        float oi = S.bufA[i];
        x0 = fmaf(oi, wp[i * 64 + o0], x0);
        x1 = fmaf(oi, wp[i * 64 + o1], x1);
    }
    #pragma unroll 4
    for (int i = 0; i < 64; ++i) {
        float si = S.short_s[i];
        x0 = fmaf(si, wp[(64 + i) * 64 + o0], x0);
        x1 = fmaf(si, wp[(64 + i) * 64 + o1], x1);
    }
    x0 += S.short_s[o0];
    x1 += S.short_s[o1];

    // ---- layernorm2 ----
    {
        float sm = x0 + x1;
        #pragma unroll
        for (int off = 16; off; off >>= 1) sm += __shfl_xor_sync(0xffffffffu, sm, off);
        float mean = sm * (1.0f / 64.0f);
        float d0 = x0 - mean, d1 = x1 - mean;
        float vs = d0 * d0 + d1 * d1;
        #pragma unroll
        for (int off = 16; off; off >>= 1) vs += __shfl_xor_sync(0xffffffffu, vs, off);
        float inv = rsqrtf(vs * (1.0f / 64.0f) + 1e-5f);
        S.bufB[o0] = d0 * inv * ln2_g[o0] + ln2_b[o0];
        S.bufB[o1] = d1 * inv * ln2_g[o1] + ln2_b[o1];
    }
    __syncwarp();

    // ---- FFN hidden ----
    {
        float a0 = fb1[o0], a1 = fb1[o1];
        #pragma unroll 4
        for (int i = 0; i < 64; ++i) {
            float xv = S.bufB[i];
            a0 = fmaf(xv, fw1[i * 64 + o0], a0);
            a1 = fmaf(xv, fw1[i * 64 + o1], a1);
        }
        S.bufA[o0] = gelu_exact(a0);
        S.bufA[o1] = gelu_exact(a1);
    }
    __syncwarp();

    // ---- FFN out + residual ----
    {
        float a0 = fb2[o0], a1 = fb2[o1];
        #pragma unroll 4
        for (int i = 0; i < 64; ++i) {
            float hv = S.bufA[i];
            a0 = fmaf(hv, fw2[i * 64 + o0], a0);
            a1 = fmaf(hv, fw2[i * 64 + o1], a1);
        }
        S.x_s[o0] = x0 + a0;
        S.x_s[o1] = x1 + a1;
    }

    // ---- block-staged transposed writeout ----
    __syncthreads();
    {
        int n0 = blockIdx.x * 4;
        int bb = n0 >> 12;
        int pix0 = n0 & 4095;
        float* cg = out + FLOW_SZ + (size_t)bb * 64 * 4096;
        for (int idx = threadIdx.x; idx < 256; idx += 128) {
            int o = idx >> 2, t = idx & 3;
            cg[o * 4096 + pix0 + t] = ts[t].x_s[o];
        }
    }
}

// ============================================================================
// Convex upsampling; blocks 0..23 transpose FTE weights, blocks 24..87
// convert wk/wv into tf32 hi/lo scratch for the GEMM kernel.
// ============================================================================
__global__ __launch_bounds__(256) void upsample_kernel(
    const float* __restrict__ coords1,
    const float* __restrict__ up_mask,
    const float* __restrict__ fte_w1,
    const float* __restrict__ fte_w2,
    const float* __restrict__ wk,
    const float* __restrict__ wv,
    float* __restrict__ out)
{
    __shared__ float slab[576 * 8];
    __shared__ float fl[2][3][10];
    __shared__ float outp[2 * 8 * 64];

    int blk = blockIdx.x;
    int tid = threadIdx.x;

    if (blk < 24) {
        int i = blk * 256 + tid;
        if (i < 81 * 64) {
            int c = i >> 6, o = i & 63;
            g_w1t[i] = fte_w1[o * 81 + c];
        }
        if (i < 64 * 64) {
            int c = i >> 6, o = i & 63;
            g_w2t[i] = fte_w2[o * 64 + c];
        }
    } else if (blk < 88) {
        int i = (blk - 24) * 256 + tid;   // [0, 16384)
        if (i < 8192) {
            float w = wk[i];
            unsigned hi = f2tf(w);
            wk_hi_g[i] = hi;
            wk_lo_g[i] = f2tf(w - __uint_as_float(hi));
        } else {
            int j = i - 8192;
            float w = wv[j];
            unsigned hi = f2tf(w);
            wv_hi_g[j] = hi;
            wv_lo_g[j] = f2tf(w - __uint_as_float(hi));
        }
    }

    int b   = blk >> 9;
    int rem = blk & 511;
    int y   = rem >> 3;
    int x0  = (rem & 7) << 3;

    const float* mbase = up_mask + (size_t)b * 576 * 4096 + y * 64 + x0;
    for (int idx = tid; idx < 576 * 8; idx += 256) {
        int ch = idx >> 3, p = idx & 7;
        slab[idx] = mbase[(size_t)ch * 4096 + p];
    }
    if (tid < 60) {
        int c = tid / 30, r2 = tid % 30, r = r2 / 10, cc = r2 % 10;
        int yy = y + r - 1, xx = x0 + cc - 1;
        float v = 0.0f;
        if ((unsigned)yy < 64u && (unsigned)xx < 64u) {
            float coord = coords1[b * 8192 + c * 4096 + yy * 64 + xx];
            v = 8.0f * (coord - (float)(c == 0 ? xx : yy));
        }
        fl[c][r][cc] = v;
    }
    __syncthreads();

    for (int q = tid; q < 512; q += 256) {
        int p  = q & 7;
        int ij = q >> 3;
        int i  = ij >> 3, j = ij & 7;
        float w[9];
        float mx = -1e30f;
        #pragma unroll
        for (int kk = 0; kk < 9; ++kk) {
            w[kk] = slab[(kk * 64 + ij) * 8 + p];
            mx = fmaxf(mx, w[kk]);
        }
        float s = 0.f;
        #pragma unroll
        for (int kk = 0; kk < 9; ++kk) { w[kk] = __expf(w[kk] - mx); s += w[kk]; }
        float inv = 1.0f / s;
        float u0 = 0.f, u1 = 0.f;
        #pragma unroll
        for (int kk = 0; kk < 9; ++kk) {
            int dy = kk / 3, dx = kk - dy * 3;
            u0 = fmaf(w[kk], fl[0][dy][p + dx], u0);
            u1 = fmaf(w[kk], fl[1][dy][p + dx], u1);
        }
        int col = p * 8 + j;
        outp[(0 * 8 + i) * 64 + col] = u0 * inv;
        outp[(1 * 8 + i) * 64 + col] = u1 * inv;
    }
    __syncthreads();

    float* obase = out + (size_t)b * 2 * 512 * 512 + (size_t)(8 * y) * 512 + 8 * x0;
    for (int idx = tid; idx < 1024; idx += 256) {
        int c = idx >> 9, rest = idx & 511;
        int i = rest >> 6, col = rest & 63;
        obase[(size_t)c * 512 * 512 + i * 512 + col] = outp[(c * 8 + i) * 64 + col];
    }
}

extern "C" void kernel_launch(void* const* d_in, const int* in_sizes, int n_in,
                              void* d_out, int out_size) {
    const float* cost_maps   = (const float*)d_in[0];
    const float* cost_memory = (const float*)d_in[1];
    const float* coords1     = (const float*)d_in[2];
    const float* up_mask     = (const float*)d_in[3];
    const float* fte_w1      = (const float*)d_in[4];
    const float* fte_b1      = (const float*)d_in[5];
    const float* fte_w2      = (const float*)d_in[6];
    const float* fte_b2      = (const float*)d_in[7];
    const float* ln1_g       = (const float*)d_in[8];
    const float* ln1_b       = (const float*)d_in[9];
    const float* ln2_g       = (const float*)d_in[10];
    const float* ln2_b       = (const float*)d_in[11];
    const float* wq          = (const float*)d_in[12];
    const float* bq          = (const float*)d_in[13];
    const float* wk          = (const float*)d_in[14];
    const float* bk          = (const float*)d_in[15];
    const float* wv          = (const float*)d_in[16];
    const float* bv          = (const float*)d_in[17];
    const float* wp          = (const float*)d_in[18];
    const float* bp          = (const float*)d_in[19];
    const float* fw1         = (const float*)d_in[20];
    const float* fb1         = (const float*)d_in[21];
    const float* fw2         = (const float*)d_in[22];
    const float* fb2         = (const float*)d_in[23];
    float* out = (float*)d_out;

    upsample_kernel<<<1024, 256>>>(coords1, up_mask, fte_w1, fte_w2, wk, wv, out);
    kv_gemm<<<512, 256>>>(cost_memory, bk, bv);
    decoder_kernel<<<2048, 128>>>(cost_maps, coords1,
                                  fte_b1, fte_b2,
                                  ln1_g, ln1_b, ln2_g, ln2_b,
                                  wq, bq, wp, bp,
                                  fw1, fb1, fw2, fb2, out);
}